// round 7
// baseline (speedup 1.0000x reference)
#include <cuda_runtime.h>
#include <cuda_fp16.h>
#include <cstdint>

#define M_TOT 32768
#define K_TOT 8192
#define D_DIM 512

// CTA tile 128(M) x 256(N), BK=16; 16 warps of 32x64; fp16 hi/lo split, 3-term.
#define BM 128
#define BN 256
#define TILES 1024                    // 32 groups * 32 k-tiles
#define A_TILE_HALF 4096              // 8KB : hi plane 4KB | lo plane 4KB
#define B_TILE_HALF 8192              // 16KB: 32 nblk * 32 lanes * 8 halves (hi|lo interleaved 16B)
#define STG_BYTES 24576               // 8KB A + 16KB B
#define NSTG 3
#define SCR_BYTES (NSTG * STG_BYTES)  // 73728
#define SMEM_BYTES (SCR_BYTES + 4096)

// ---- device scratch -----------------------------------------------------------
__device__ float  g_hn[K_TOT];
__device__ int    g_idx[M_TOT];
__device__ __half g_A[(size_t)M_TOT * D_DIM * 2];   // 64MB fragment-packed, hi/lo PLANES per tile
__device__ __half g_B[(size_t)K_TOT * D_DIM * 2];   // 16MB fragment-packed hi|lo (L2-resident)

// ---- helpers --------------------------------------------------------------------
__device__ __forceinline__ uint32_t smem_u32(const void* p) {
    uint32_t a;
    asm("{ .reg .u64 t; cvta.to.shared.u64 t, %1; cvt.u32.u64 %0, t; }" : "=r"(a) : "l"(p));
    return a;
}
__device__ __forceinline__ void cp16(uint32_t dst, const void* src) {
    asm volatile("cp.async.cg.shared.global [%0], [%1], 16;" :: "r"(dst), "l"(src) : "memory");
}
#define CP_COMMIT() asm volatile("cp.async.commit_group;" ::: "memory")
#define CP_WAIT1()  asm volatile("cp.async.wait_group 1;" ::: "memory")
#define CP_WAIT0()  asm volatile("cp.async.wait_group 0;" ::: "memory")

__device__ __forceinline__ void mma16(float* c, const uint4& a, uint32_t b0, uint32_t b1) {
    asm volatile(
        "mma.sync.aligned.m16n8k16.row.col.f32.f16.f16.f32 "
        "{%0,%1,%2,%3}, {%4,%5,%6,%7}, {%8,%9}, {%0,%1,%2,%3};"
        : "+f"(c[0]), "+f"(c[1]), "+f"(c[2]), "+f"(c[3])
        : "r"(a.x), "r"(a.y), "r"(a.z), "r"(a.w), "r"(b0), "r"(b1));
}

// ---- prep: fp16 hi/lo split + permute into m16n8k16 fragment order --------------
// lane = q*4 + r4. A tile layout: hi plane [mblk(8)][lane(32)][8 halves] (4KB),
// then lo plane at +2048 halves. Conflict-free 16B/lane loads.
__global__ void pack_ze(const float* __restrict__ ze) {
    int i = blockIdx.x * blockDim.x + threadIdx.x;
    float f = ze[i];
    __half hi = __float2half_rn(f);
    __half lo = __float2half_rn(f - __half2float(hi));
    int m = i >> 9, d = i & 511;
    int mt = m >> 7, mr = m & 127, mblk = mr >> 4, row = mr & 15;
    int q = row & 7, rhalf = row >> 3;
    int kt = d >> 4, kk = d & 15, par = kk & 1, r4 = (kk >> 1) & 3, khalf = kk >> 3;
    int lane = q * 4 + r4, reg = rhalf + 2 * khalf;
    size_t base = ((size_t)(mt * 32 + kt)) * A_TILE_HALF + (size_t)(mblk * 32 + lane) * 8;
    g_A[base + reg * 2 + par]        = hi;   // hi plane
    g_A[base + 2048 + reg * 2 + par] = lo;   // lo plane
}
// B element (col n, k): q = n&7 (groupID), k: par=k&1, r4=(k>>1)&3, khalf=k>>3 (reg).
__global__ void pack_cb(const float* __restrict__ cb) {
    int i = blockIdx.x * blockDim.x + threadIdx.x;
    float f = cb[i];
    __half hi = __float2half_rn(f);
    __half lo = __float2half_rn(f - __half2float(hi));
    int n = i >> 9, d = i & 511;
    int g = n >> 8, nr = n & 255, nblk = nr >> 3, q = nr & 7;
    int kt = d >> 4, kk = d & 15, par = kk & 1, r4 = (kk >> 1) & 3, khalf = kk >> 3;
    int lane = q * 4 + r4;
    size_t base = ((size_t)(g * 32 + kt)) * B_TILE_HALF + (size_t)(nblk * 32 + lane) * 8;
    g_B[base + khalf * 2 + par]     = hi;
    g_B[base + 4 + khalf * 2 + par] = lo;
}
__global__ void norm_kernel(const float* __restrict__ cb) {
    int warp = (blockIdx.x * blockDim.x + threadIdx.x) >> 5;
    int lane = threadIdx.x & 31;
    const float4* row = reinterpret_cast<const float4*>(cb + (size_t)warp * D_DIM);
    float s = 0.0f;
#pragma unroll
    for (int t = 0; t < 4; ++t) {
        float4 v = row[lane + 32 * t];
        s += v.x * v.x + v.y * v.y + v.z * v.z + v.w * v.w;
    }
#pragma unroll
    for (int off = 16; off > 0; off >>= 1) s += __shfl_xor_sync(0xffffffffu, s, off);
    if (lane == 0) g_hn[warp] = 0.5f * s;
}

// ---- main fused GEMM + argmin ----------------------------------------------------
__global__ void __launch_bounds__(512, 2) vq_mma_kernel() {
    extern __shared__ __align__(16) char smem[];
    const uint32_t sbase = smem_u32(smem);

    const int tid  = threadIdx.x;
    const int wid  = tid >> 5, lane = tid & 31;
    const int wm   = wid >> 2;          // 0..3 : 32-row group
    const int wn   = wid & 3;           // 0..3 : 64-col group
    const int q    = lane >> 2;         // 0..7
    const int r4   = lane & 3;          // 0..3
    const int m0   = blockIdx.x * BM;

    float* s_sb = reinterpret_cast<float*>(smem + SCR_BYTES);
    int*   s_si = reinterpret_cast<int*>(smem + SCR_BYTES + 2048);

    float acc[2][8][4];
    float bestv[2][2];
    int   besti[2][2];
#pragma unroll
    for (int mf = 0; mf < 2; ++mf) {
#pragma unroll
        for (int h = 0; h < 2; ++h) { bestv[mf][h] = -3.0e38f; besti[mf][h] = 0; }
#pragma unroll
        for (int nf = 0; nf < 8; ++nf)
#pragma unroll
            for (int c = 0; c < 4; ++c) acc[mf][nf][c] = 0.0f;
    }

    auto issue_tile = [&](int t) {
        const uint32_t stw = sbase + (uint32_t)(t % NSTG) * STG_BYTES;
        const __half* aG = g_A + ((size_t)(blockIdx.x * 32) + (t & 31)) * A_TILE_HALF;
        const __half* bG = g_B + ((size_t)((t >> 5) * 32 + (t & 31))) * B_TILE_HALF;
        // A: 512 x 16B segs (hi plane then lo plane, contiguous 8KB)
        cp16(stw + tid * 16, aG + tid * 8);
        // B: 1024 x 16B segs
#pragma unroll
        for (int i = 0; i < 2; ++i) {
            int seg = tid + i * 512;
            cp16(stw + 8192 + seg * 16, bG + seg * 8);
        }
        CP_COMMIT();
    };

    issue_tile(0);
    issue_tile(1);

    for (int t = 0; t < TILES; ++t) {
        if (t < TILES - 1) { CP_WAIT1(); } else { CP_WAIT0(); }
        __syncthreads();
        if (t + 2 < TILES) issue_tile(t + 2);

        const char* st = smem + (t % NSTG) * STG_BYTES;

        uint4 ah[2], al[2];
#pragma unroll
        for (int mf = 0; mf < 2; ++mf) {
            // hi plane: conflict-free 16B/lane
            ah[mf] = *reinterpret_cast<const uint4*>(
                st + (size_t)((wm * 2 + mf) * 32 + lane) * 16);
            // lo plane at +4096B: conflict-free 16B/lane
            al[mf] = *reinterpret_cast<const uint4*>(
                st + 4096 + (size_t)((wm * 2 + mf) * 32 + lane) * 16);
        }
#pragma unroll
        for (int nf = 0; nf < 8; ++nf) {
            uint4 b = *reinterpret_cast<const uint4*>(
                st + 8192 + (size_t)((wn * 8 + nf) * 32 + lane) * 16);
#pragma unroll
            for (int mf = 0; mf < 2; ++mf) {
                mma16(acc[mf][nf], ah[mf], b.x, b.y);   // hi*hi
                mma16(acc[mf][nf], ah[mf], b.z, b.w);   // hi*lo
                mma16(acc[mf][nf], al[mf], b.x, b.y);   // lo*hi  (lo*lo dropped: ~2^-22)
            }
        }

        if ((t & 31) == 31) {                         // group done: fold argmax
            const int g = t >> 5;
#pragma unroll
            for (int nf = 0; nf < 8; ++nf) {
                int gc = g * BN + wn * 64 + nf * 8 + 2 * r4;
                float h0 = __ldg(&g_hn[gc]), h1 = __ldg(&g_hn[gc + 1]);
#pragma unroll
                for (int mf = 0; mf < 2; ++mf) {
                    float s0 = acc[mf][nf][0] - h0, s1 = acc[mf][nf][1] - h1;
                    float s2 = acc[mf][nf][2] - h0, s3 = acc[mf][nf][3] - h1;
                    if (s0 > bestv[mf][0]) { bestv[mf][0] = s0; besti[mf][0] = gc; }
                    if (s1 > bestv[mf][0]) { bestv[mf][0] = s1; besti[mf][0] = gc + 1; }
                    if (s2 > bestv[mf][1]) { bestv[mf][1] = s2; besti[mf][1] = gc; }
                    if (s3 > bestv[mf][1]) { bestv[mf][1] = s3; besti[mf][1] = gc + 1; }
                    acc[mf][nf][0] = 0.0f; acc[mf][nf][1] = 0.0f;
                    acc[mf][nf][2] = 0.0f; acc[mf][nf][3] = 0.0f;
                }
            }
        }
    }

    // Merge the 4 lanes of each quad (lane = q*4 + r4; xor 1,2 stay in-quad).
#pragma unroll
    for (int off = 1; off <= 2; off <<= 1) {
#pragma unroll
        for (int mf = 0; mf < 2; ++mf)
#pragma unroll
            for (int h = 0; h < 2; ++h) {
                float ov = __shfl_xor_sync(0xffffffffu, bestv[mf][h], off);
                int   oi = __shfl_xor_sync(0xffffffffu, besti[mf][h], off);
                if (ov > bestv[mf][h] || (ov == bestv[mf][h] && oi < besti[mf][h])) {
                    bestv[mf][h] = ov; besti[mf][h] = oi;
                }
            }
    }
    if (r4 == 0) {
#pragma unroll
        for (int mf = 0; mf < 2; ++mf)
#pragma unroll
            for (int h = 0; h < 2; ++h) {
                int rl = wm * 32 + mf * 16 + h * 8 + q;
                s_sb[rl * 4 + wn] = bestv[mf][h];
                s_si[rl * 4 + wn] = besti[mf][h];
            }
    }
    __syncthreads();
    if (tid < BM) {
        float bv = s_sb[tid * 4]; int bi = s_si[tid * 4];
#pragma unroll
        for (int w = 1; w < 4; ++w) {
            float ov = s_sb[tid * 4 + w]; int oi = s_si[tid * 4 + w];
            if (ov > bv || (ov == bv && oi < bi)) { bv = ov; bi = oi; }
        }
        g_idx[m0 + tid] = bi;
    }
}

// ---- gather ------------------------------------------------------------------------
__global__ void gather_kernel(const float* __restrict__ cb, float* __restrict__ out) {
    int m = blockIdx.x;
    int k = g_idx[m];
    const float4* src = reinterpret_cast<const float4*>(cb + (size_t)k * D_DIM);
    float4*       dst = reinterpret_cast<float4*>(out + (size_t)m * D_DIM);
    dst[threadIdx.x] = src[threadIdx.x];
}

// ---- entry ---------------------------------------------------------------------------
extern "C" void kernel_launch(void* const* d_in, const int* in_sizes, int n_in,
                              void* d_out, int out_size) {
    const float* ze = (const float*)d_in[0];
    const float* cb = (const float*)d_in[1];
    float* out = (float*)d_out;

    cudaFuncSetAttribute(vq_mma_kernel, cudaFuncAttributeMaxDynamicSharedMemorySize, SMEM_BYTES);

    pack_ze<<<(M_TOT * D_DIM) / 256, 256>>>(ze);
    pack_cb<<<(K_TOT * D_DIM) / 256, 256>>>(cb);
    norm_kernel<<<K_TOT / 8, 256>>>(cb);
    vq_mma_kernel<<<M_TOT / BM, 512, SMEM_BYTES>>>();
    gather_kernel<<<M_TOT, 128>>>(cb, out);
}